// round 13
// baseline (speedup 1.0000x reference)
#include <cuda_runtime.h>
#include <cuda_fp8.h>
#include <cstdint>
#include <cmath>

// ---------------------------------------------------------------------------
// BinaryConv2dBBCU_Down via Winograd F(2x2,3x3), all-exact arithmetic:
//   d in {-1,0,1}  -> V = Bt d B   integers |<=4|   (e4m3 exact)
//   w in {-1,0,1}  -> U = G w Gt   multiples of 1/4 (e4m3 exact)
//   m = sum_ch V.U (fp32, dyadic, exact) ; y = At m A (exact integers)
// 2.25x fewer tensor MACs than direct conv (4.19M vs 9.44M QMMA).
// ---------------------------------------------------------------------------

#define NB   8
#define CINC 128
#define COC  256
#define HPAD 130
#define AP   144
#define NBLK 2048                    // 16-tile M-blocks (32768 tiles total)

// device scratch
__device__ __align__(256) signed char   g_act[(size_t)NB * HPAD * HPAD * CINC];   // +-1 codes
__device__ __align__(256) unsigned char g_V[(size_t)NBLK * 16 * 16 * AP];         // [blk][pos][tile][144]
__device__ __align__(256) unsigned char g_U[(size_t)4 * 16 * 64 * AP];            // [nq][pos][oc64][144]
__device__ float g_wscale[COC];

// ------------------------------------------------------------- PTX helpers
__device__ __forceinline__ void bulkcp(uint32_t dst, const void* src, uint32_t bytes,
                                       uint32_t mbar) {
    asm volatile("cp.async.bulk.shared::cta.global.mbarrier::complete_tx::bytes "
                 "[%0], [%1], %2, [%3];"
                 :: "r"(dst), "l"(src), "r"(bytes), "r"(mbar) : "memory");
}
__device__ __forceinline__ void mbar_init(uint32_t a, uint32_t cnt) {
    asm volatile("mbarrier.init.shared.b64 [%0], %1;" :: "r"(a), "r"(cnt) : "memory");
}
__device__ __forceinline__ void mbar_expect(uint32_t a, uint32_t bytes) {
    asm volatile("mbarrier.arrive.expect_tx.shared.b64 _, [%0], %1;"
                 :: "r"(a), "r"(bytes) : "memory");
}
__device__ __forceinline__ void mbar_arrive(uint32_t a) {
    asm volatile("mbarrier.arrive.shared.b64 _, [%0];" :: "r"(a) : "memory");
}
__device__ __forceinline__ void mbar_wait(uint32_t a, uint32_t parity) {
    asm volatile(
        "{\n\t.reg .pred P1;\n\t"
        "WAIT_%=:\n\t"
        "mbarrier.try_wait.parity.acquire.cta.shared::cta.b64 P1, [%0], %1, 0x989680;\n\t"
        "@P1 bra.uni DONE_%=;\n\t"
        "bra.uni WAIT_%=;\n\t"
        "DONE_%=:\n\t}"
        :: "r"(a), "r"(parity) : "memory");
}
__device__ __forceinline__ void ldsm4(uint32_t& r0, uint32_t& r1, uint32_t& r2, uint32_t& r3,
                                      uint32_t a) {
    asm volatile("ldmatrix.sync.aligned.m8n8.x4.shared.b16 {%0,%1,%2,%3},[%4];\n"
                 : "=r"(r0), "=r"(r1), "=r"(r2), "=r"(r3) : "r"(a));
}
__device__ __forceinline__ void mma16832f8(float* c, const uint32_t* a, const uint32_t* b) {
    asm volatile("mma.sync.aligned.m16n8k32.row.col.f32.e4m3.e4m3.f32 "
                 "{%0,%1,%2,%3},{%4,%5,%6,%7},{%8,%9},{%0,%1,%2,%3};\n"
                 : "+f"(c[0]), "+f"(c[1]), "+f"(c[2]), "+f"(c[3])
                 : "r"(a[0]), "r"(a[1]), "r"(a[2]), "r"(a[3]), "r"(b[0]), "r"(b[1]));
}

// e4m3 code for small integers v in [-4,4] (exact)
__device__ __forceinline__ uint32_t e4m3_int(int v) {
    int a = v < 0 ? -v : v;
    uint32_t mag = a ? ((0x48444038u >> (8 * (a - 1))) & 0xffu) : 0u;
    return v < 0 ? (mag | 0x80u) : mag;
}

// ------------------------- pool + bias + sign (+ halo zeroing fused)
__global__ void __launch_bounds__(256) prep_kernel(const float* __restrict__ x,
                                                   const float* __restrict__ mbias) {
    const int y = blockIdx.x, b = blockIdx.y;
    const int tid = threadIdx.x, lane = tid & 31, wrp = tid >> 5;

    __shared__ signed char st[128 * 136];

    for (int k = 0; k < 16; ++k) {
        const int c = wrp + 8 * k;
        const float* r0 = x + ((size_t)(b * CINC + c) * 256 + 2 * y) * 256;
        const float* r1 = r0 + 256;
        const float bias = __ldg(mbias + c);
#pragma unroll
        for (int xb = 0; xb < 2; ++xb) {
            const int xo = xb * 64 + lane * 2;
            float4 u = *reinterpret_cast<const float4*>(r0 + 2 * xo);
            float4 v = *reinterpret_cast<const float4*>(r1 + 2 * xo);
            float p0 = (u.x + u.y + v.x + v.y) * 0.25f + bias;
            float p1 = (u.z + u.w + v.z + v.w) * 0.25f + bias;
            st[xo * 136 + c]       = p0 > 0.f ? 1 : (p0 < 0.f ? -1 : 0);
            st[(xo + 1) * 136 + c] = p1 > 0.f ? 1 : (p1 < 0.f ? -1 : 0);
        }
    }
    __syncthreads();

    // interior padded row (y+1), cols 1..128, pitch 128
    uint32_t* dst = reinterpret_cast<uint32_t*>(
        g_act + ((size_t)(b * HPAD + (y + 1)) * HPAD) * CINC);
    const char* sp = reinterpret_cast<const char*>(st);
    for (int i = tid; i < 128 * 32; i += 256) {
        const int xr = i >> 5, wd = i & 31;
        dst[(xr + 1) * 32 + wd] = *reinterpret_cast<const uint32_t*>(sp + xr * 136 + wd * 4);
    }

    uint32_t* base = reinterpret_cast<uint32_t*>(g_act + ((size_t)b * HPAD * HPAD) * CINC);
    if (y == 0) {
        for (int i = tid; i < HPAD * 32; i += 256) base[i] = 0u;
    } else if (y == 127) {
        uint32_t* r129 = base + (size_t)129 * HPAD * 32;
        for (int i = tid; i < HPAD * 32; i += 256) r129[i] = 0u;
    }
    uint32_t* rowp = base + (size_t)(y + 1) * HPAD * 32;
    if (tid < 32) rowp[tid] = 0u;
    else if (tid < 64) rowp[129 * 32 + (tid - 32)] = 0u;
}

// ------------------------------- weight: scale + Winograd U = G w Gt (e4m3)
__global__ void wprep_kernel(const float* __restrict__ w) {
    const int oc = blockIdx.x, c = threadIdx.x;   // 256 x 128
    const float* wp = w + ((size_t)oc * CINC + c) * 9;
    float v[9]; float s = 0.f;
#pragma unroll
    for (int i = 0; i < 9; ++i) { v[i] = wp[i]; s += fabsf(v[i]); }

    __shared__ float red[128];
    red[c] = s; __syncthreads();
    for (int o = 64; o > 0; o >>= 1) { if (c < o) red[c] += red[c + o]; __syncthreads(); }
    if (c == 0) g_wscale[oc] = red[0] * (1.f / 1152.f);

    float sg[9];
#pragma unroll
    for (int i = 0; i < 9; ++i) sg[i] = v[i] > 0.f ? 1.f : (v[i] < 0.f ? -1.f : 0.f);

    // h = G * w (4x3), u = h * Gt (4x4); all dyadic, e4m3-exact
    float h[4][3];
#pragma unroll
    for (int j = 0; j < 3; ++j) {
        h[0][j] = sg[j];
        h[1][j] = 0.5f * (sg[j] + sg[3 + j] + sg[6 + j]);
        h[2][j] = 0.5f * (sg[j] - sg[3 + j] + sg[6 + j]);
        h[3][j] = sg[6 + j];
    }
    const int nq = oc >> 6, ocl = oc & 63;
#pragma unroll
    for (int r = 0; r < 4; ++r) {
        float a = h[r][0], bb = h[r][1], cc = h[r][2];
        float u0 = a, u1 = 0.5f * (a + bb + cc), u2 = 0.5f * (a - bb + cc), u3 = cc;
        float uu[4] = {u0, u1, u2, u3};
#pragma unroll
        for (int q = 0; q < 4; ++q) {
            const int p = r * 4 + q;
            g_U[((size_t)(nq * 16 + p) * 64 + ocl) * AP + c] =
                (unsigned char)__nv_cvt_float_to_fp8(uu[q], __NV_SATFINITE, __NV_E4M3);
        }
    }
}

// ----------------------------------- input transform V = Bt d B -> e4m3
__global__ void __launch_bounds__(256) vtrans_kernel() {
    const int vb = blockIdx.x;                 // 0..2047
    const int b = vb >> 8, rr = vb & 255;
    const int trow = rr >> 2, tcb = (rr & 3) * 16;
    const int tid = threadIdx.x;
    const int c4 = (tid & 31) * 4;

    for (int tt = 0; tt < 2; ++tt) {
        const int tloc = (tid >> 5) * 2 + tt;
        const int tx = tcb + tloc;
        uint32_t dw[16];
#pragma unroll
        for (int r = 0; r < 4; ++r)
#pragma unroll
            for (int cx = 0; cx < 4; ++cx)
                dw[r * 4 + cx] = __ldg(reinterpret_cast<const uint32_t*>(
                    g_act + ((size_t)((b * HPAD + 2 * trow + r) * HPAD) + 2 * tx + cx) * CINC + c4));

        uint32_t outp[16];
#pragma unroll
        for (int p = 0; p < 16; ++p) outp[p] = 0u;

#pragma unroll
        for (int ch = 0; ch < 4; ++ch) {
            int d[16];
#pragma unroll
            for (int i = 0; i < 16; ++i)
                d[i] = (int)(signed char)((dw[i] >> (8 * ch)) & 0xff);
            int e[16];
#pragma unroll
            for (int cx = 0; cx < 4; ++cx) {
                e[cx]      = d[cx] - d[8 + cx];
                e[4 + cx]  = d[4 + cx] + d[8 + cx];
                e[8 + cx]  = d[8 + cx] - d[4 + cx];
                e[12 + cx] = d[4 + cx] - d[12 + cx];
            }
#pragma unroll
            for (int r = 0; r < 4; ++r) {
                const int bs = r * 4;
                int V0 = e[bs] - e[bs + 2];
                int V1 = e[bs + 1] + e[bs + 2];
                int V2 = e[bs + 2] - e[bs + 1];
                int V3 = e[bs + 1] - e[bs + 3];
                outp[bs]     |= e4m3_int(V0) << (8 * ch);
                outp[bs + 1] |= e4m3_int(V1) << (8 * ch);
                outp[bs + 2] |= e4m3_int(V2) << (8 * ch);
                outp[bs + 3] |= e4m3_int(V3) << (8 * ch);
            }
        }
#pragma unroll
        for (int p = 0; p < 16; ++p)
            *reinterpret_cast<uint32_t*>(
                g_V + ((size_t)(vb * 16 + p) * 16 + tloc) * AP + c4) = outp[p];
    }
}

// ---------------------------------------------------------------- GEMM + At m A
#define V_SMEM  36864                       // 16 pos x 16 tiles x 144
#define U_BUF   18432                       // 2 pos x 64 oc x 144
#define BAR_OFF (V_SMEM + 2 * U_BUF)        // 73728
#define SMEM_TOT (BAR_OFF + 64)

__global__ void __launch_bounds__(256, 2) gemm_kernel(
    float* __restrict__ out,
    const float* __restrict__ pb0, const float* __restrict__ alpha,
    const float* __restrict__ pb1)
{
    extern __shared__ char smem[];
    const int nq = blockIdx.x;                // oc quarter
    const int mb = blockIdx.y;                // 16-tile block
    const int tid = threadIdx.x, lane = tid & 31, w = tid >> 5;

    const uint32_t sbase = (uint32_t)__cvta_generic_to_shared(smem);
    const uint32_t FULL0 = sbase + BAR_OFF, FULL1 = sbase + BAR_OFF + 8;
    const uint32_t EMPT0 = sbase + BAR_OFF + 16, EMPT1 = sbase + BAR_OFF + 24;

    if (tid == 0) {
        mbar_init(FULL0, 1); mbar_init(FULL1, 1);
        mbar_init(EMPT0, 256); mbar_init(EMPT1, 256);
    }
    __syncthreads();

    const unsigned char* vsrc = g_V + (size_t)mb * V_SMEM;
    const unsigned char* usrc = g_U + (size_t)nq * 16 * 64 * AP;

    if (tid == 0) {
        mbar_expect(FULL0, V_SMEM + U_BUF);
        bulkcp(sbase, vsrc, V_SMEM, FULL0);                      // all 16 pos of V
        bulkcp(sbase + V_SMEM, usrc, U_BUF, FULL0);              // pos 0-1
        mbar_expect(FULL1, U_BUF);
        bulkcp(sbase + V_SMEM + U_BUF, usrc + U_BUF, U_BUF, FULL1); // pos 2-3
    }

    float acc[16][4];
#pragma unroll
    for (int p = 0; p < 16; ++p)
#pragma unroll
        for (int j = 0; j < 4; ++j) acc[p][j] = 0.f;

    // validated fragment addressing
    const int lrow = lane & 7, grp = lane >> 3;
    const uint32_t laneA = (uint32_t)(((grp & 1) * 8 + lrow) * AP + (grp >> 1) * 16);
    // B ldsm4: grp0/1 -> pos pp0 (kh0/kh16), grp2/3 -> pos pp0+1
    const uint32_t laneB = (uint32_t)((grp >> 1) * (64 * AP) + (w * 8 + lrow) * AP + (grp & 1) * 16);

#pragma unroll
    for (int g = 0; g < 8; ++g) {
        mbar_wait((g & 1) ? FULL1 : FULL0, (g >> 1) & 1);
        const uint32_t ub = sbase + V_SMEM + (g & 1) * U_BUF;
        const int p0 = 2 * g;

#pragma unroll
        for (int k0 = 0; k0 < 4; ++k0) {
            uint32_t a0[4], a1[4], r0, r1, r2, r3;
            ldsm4(a0[0], a0[1], a0[2], a0[3], sbase + p0 * (16 * AP) + laneA + k0 * 32);
            ldsm4(a1[0], a1[1], a1[2], a1[3], sbase + (p0 + 1) * (16 * AP) + laneA + k0 * 32);
            ldsm4(r0, r1, r2, r3, ub + laneB + k0 * 32);
            uint32_t b01[2] = {r0, r1}, b23[2] = {r2, r3};
            mma16832f8(acc[p0], a0, b01);
            mma16832f8(acc[p0 + 1], a1, b23);
        }

        if (g < 6) {
            mbar_arrive((g & 1) ? EMPT1 : EMPT0);
            if (tid == 0) {
                mbar_wait((g & 1) ? EMPT1 : EMPT0, (g >> 1) & 1);
                mbar_expect((g & 1) ? FULL1 : FULL0, U_BUF);
                bulkcp(sbase + V_SMEM + (g & 1) * U_BUF,
                       usrc + (size_t)(2 * (g + 2)) * (64 * AP) / 2 * 2, U_BUF,
                       (g & 1) ? FULL1 : FULL0);
            }
        }
    }

    // --- epilogue: At m A + scale/bias/PReLU/bias, per-thread registers only ---
    const int b = mb >> 8, rr = mb & 255;
    const int trow = rr >> 2, tcb = (rr & 3) * 16;

#pragma unroll
    for (int j = 0; j < 4; ++j) {
        const int tloc = (lane >> 2) + (j >> 1) * 8;       // tile within block
        const int oc = nq * 64 + w * 8 + (lane & 3) * 2 + (j & 1);
        const float sc = g_wscale[oc];
        const float c0 = __ldg(pb0 + oc);
        const float al = __ldg(alpha + oc);
        const float d1 = __ldg(pb1 + oc);

        float s0[4], s1[4];
#pragma unroll
        for (int cx = 0; cx < 4; ++cx) {
            s0[cx] = acc[cx][j] + acc[4 + cx][j] + acc[8 + cx][j];
            s1[cx] = acc[4 + cx][j] - acc[8 + cx][j] - acc[12 + cx][j];
        }
        float y00 = s0[0] + s0[1] + s0[2], y01 = s0[1] - s0[2] - s0[3];
        float y10 = s1[0] + s1[1] + s1[2], y11 = s1[1] - s1[2] - s1[3];

        const int tcol = tcb + tloc;
        float* op = out + (((size_t)(b * COC + oc) * 128 + 2 * trow) * 128 + 2 * tcol);
        float v;
        float2 o0, o1;
        v = y00 * sc + c0; v = v >= 0.f ? v : v * al; o0.x = v + d1;
        v = y01 * sc + c0; v = v >= 0.f ? v : v * al; o0.y = v + d1;
        v = y10 * sc + c0; v = v >= 0.f ? v : v * al; o1.x = v + d1;
        v = y11 * sc + c0; v = v >= 0.f ? v : v * al; o1.y = v + d1;
        *reinterpret_cast<float2*>(op) = o0;
        *reinterpret_cast<float2*>(op + 128) = o1;
    }
}

// ---------------------------------------------------------------- launcher
extern "C" void kernel_launch(void* const* d_in, const int* in_sizes, int n_in,
                              void* d_out, int out_size) {
    const float* x   = (const float*)d_in[0];
    const float* wt  = (const float*)d_in[1];
    const float* mb  = (const float*)d_in[2];
    const float* pb0 = (const float*)d_in[3];
    const float* al  = (const float*)d_in[4];
    const float* pb1 = (const float*)d_in[5];
    float* out = (float*)d_out;

    cudaFuncSetAttribute(gemm_kernel, cudaFuncAttributeMaxDynamicSharedMemorySize, SMEM_TOT);

    prep_kernel<<<dim3(128, NB), 256>>>(x, mb);
    wprep_kernel<<<COC, 128>>>(wt);
    vtrans_kernel<<<NBLK, 256>>>();
    gemm_kernel<<<dim3(4, NBLK), 256, SMEM_TOT>>>(out, pb0, al, pb1);
}

// round 14
// speedup vs baseline: 1.1040x; 1.1040x over previous
#include <cuda_runtime.h>
#include <cuda_fp8.h>
#include <cstdint>
#include <cmath>

// ---------------------------------------------------------------------------
// BinaryConv2dBBCU_Down via Winograd F(2x2,3x3), all-exact arithmetic:
//   d in {-1,0,1}  -> V = Bt d B   integers |<=4|   (e4m3 exact)
//   w in {-1,0,1}  -> U = G w Gt   multiples of 1/4 (e4m3 exact)
//   m = sum_ch V.U (fp32 dyadic exact) ; y = At m A folded incrementally.
// GEMM CTA: M=32 tiles x N=128 oc, V+U streamed in 2-pos chunks; staged
// smem traffic cut 2.2x vs R13 (the measured LTS bottleneck).
// ---------------------------------------------------------------------------

#define NB   8
#define CINC 128
#define COC  256
#define HPAD 130
#define AP   144
#define NMB  1024                    // 32-tile M-blocks (32768 tiles total)

// device scratch
__device__ __align__(256) signed char   g_act[(size_t)NB * HPAD * HPAD * CINC];   // +-1 codes
__device__ __align__(256) unsigned char g_V[(size_t)NMB * 16 * 32 * AP];          // [mb][pos][tile32][144]
__device__ __align__(256) unsigned char g_U[(size_t)2 * 16 * 128 * AP];           // [nh][pos][oc128][144]
__device__ float g_wscale[COC];

// ------------------------------------------------------------- PTX helpers
__device__ __forceinline__ void bulkcp(uint32_t dst, const void* src, uint32_t bytes,
                                       uint32_t mbar) {
    asm volatile("cp.async.bulk.shared::cta.global.mbarrier::complete_tx::bytes "
                 "[%0], [%1], %2, [%3];"
                 :: "r"(dst), "l"(src), "r"(bytes), "r"(mbar) : "memory");
}
__device__ __forceinline__ void mbar_init(uint32_t a, uint32_t cnt) {
    asm volatile("mbarrier.init.shared.b64 [%0], %1;" :: "r"(a), "r"(cnt) : "memory");
}
__device__ __forceinline__ void mbar_expect(uint32_t a, uint32_t bytes) {
    asm volatile("mbarrier.arrive.expect_tx.shared.b64 _, [%0], %1;"
                 :: "r"(a), "r"(bytes) : "memory");
}
__device__ __forceinline__ void mbar_arrive(uint32_t a) {
    asm volatile("mbarrier.arrive.shared.b64 _, [%0];" :: "r"(a) : "memory");
}
__device__ __forceinline__ void mbar_wait(uint32_t a, uint32_t parity) {
    asm volatile(
        "{\n\t.reg .pred P1;\n\t"
        "WAIT_%=:\n\t"
        "mbarrier.try_wait.parity.acquire.cta.shared::cta.b64 P1, [%0], %1, 0x989680;\n\t"
        "@P1 bra.uni DONE_%=;\n\t"
        "bra.uni WAIT_%=;\n\t"
        "DONE_%=:\n\t}"
        :: "r"(a), "r"(parity) : "memory");
}
__device__ __forceinline__ void ldsm4(uint32_t& r0, uint32_t& r1, uint32_t& r2, uint32_t& r3,
                                      uint32_t a) {
    asm volatile("ldmatrix.sync.aligned.m8n8.x4.shared.b16 {%0,%1,%2,%3},[%4];\n"
                 : "=r"(r0), "=r"(r1), "=r"(r2), "=r"(r3) : "r"(a));
}
__device__ __forceinline__ void mma16832f8(float* c, const uint32_t* a, const uint32_t* b) {
    asm volatile("mma.sync.aligned.m16n8k32.row.col.f32.e4m3.e4m3.f32 "
                 "{%0,%1,%2,%3},{%4,%5,%6,%7},{%8,%9},{%0,%1,%2,%3};\n"
                 : "+f"(c[0]), "+f"(c[1]), "+f"(c[2]), "+f"(c[3])
                 : "r"(a[0]), "r"(a[1]), "r"(a[2]), "r"(a[3]), "r"(b[0]), "r"(b[1]));
}

// e4m3 code for small integers v in [-4,4] (exact)
__device__ __forceinline__ uint32_t e4m3_int(int v) {
    int a = v < 0 ? -v : v;
    uint32_t mag = a ? ((0x48444038u >> (8 * (a - 1))) & 0xffu) : 0u;
    return v < 0 ? (mag | 0x80u) : mag;
}

// ------------------------- pool + bias + sign (+ halo zeroing fused)
__global__ void __launch_bounds__(256) prep_kernel(const float* __restrict__ x,
                                                   const float* __restrict__ mbias) {
    const int y = blockIdx.x, b = blockIdx.y;
    const int tid = threadIdx.x, lane = tid & 31, wrp = tid >> 5;

    __shared__ signed char st[128 * 136];

    for (int k = 0; k < 16; ++k) {
        const int c = wrp + 8 * k;
        const float* r0 = x + ((size_t)(b * CINC + c) * 256 + 2 * y) * 256;
        const float* r1 = r0 + 256;
        const float bias = __ldg(mbias + c);
#pragma unroll
        for (int xb = 0; xb < 2; ++xb) {
            const int xo = xb * 64 + lane * 2;
            float4 u = *reinterpret_cast<const float4*>(r0 + 2 * xo);
            float4 v = *reinterpret_cast<const float4*>(r1 + 2 * xo);
            float p0 = (u.x + u.y + v.x + v.y) * 0.25f + bias;
            float p1 = (u.z + u.w + v.z + v.w) * 0.25f + bias;
            st[xo * 136 + c]       = p0 > 0.f ? 1 : (p0 < 0.f ? -1 : 0);
            st[(xo + 1) * 136 + c] = p1 > 0.f ? 1 : (p1 < 0.f ? -1 : 0);
        }
    }
    __syncthreads();

    uint32_t* dst = reinterpret_cast<uint32_t*>(
        g_act + ((size_t)(b * HPAD + (y + 1)) * HPAD) * CINC);
    const char* sp = reinterpret_cast<const char*>(st);
    for (int i = tid; i < 128 * 32; i += 256) {
        const int xr = i >> 5, wd = i & 31;
        dst[(xr + 1) * 32 + wd] = *reinterpret_cast<const uint32_t*>(sp + xr * 136 + wd * 4);
    }

    uint32_t* base = reinterpret_cast<uint32_t*>(g_act + ((size_t)b * HPAD * HPAD) * CINC);
    if (y == 0) {
        for (int i = tid; i < HPAD * 32; i += 256) base[i] = 0u;
    } else if (y == 127) {
        uint32_t* r129 = base + (size_t)129 * HPAD * 32;
        for (int i = tid; i < HPAD * 32; i += 256) r129[i] = 0u;
    }
    uint32_t* rowp = base + (size_t)(y + 1) * HPAD * 32;
    if (tid < 32) rowp[tid] = 0u;
    else if (tid < 64) rowp[129 * 32 + (tid - 32)] = 0u;
}

// ------------------------------- weight: scale + Winograd U = G w Gt (e4m3)
__global__ void wprep_kernel(const float* __restrict__ w) {
    const int oc = blockIdx.x, c = threadIdx.x;   // 256 x 128
    const float* wp = w + ((size_t)oc * CINC + c) * 9;
    float v[9]; float s = 0.f;
#pragma unroll
    for (int i = 0; i < 9; ++i) { v[i] = wp[i]; s += fabsf(v[i]); }

    __shared__ float red[128];
    red[c] = s; __syncthreads();
    for (int o = 64; o > 0; o >>= 1) { if (c < o) red[c] += red[c + o]; __syncthreads(); }
    if (c == 0) g_wscale[oc] = red[0] * (1.f / 1152.f);

    float sg[9];
#pragma unroll
    for (int i = 0; i < 9; ++i) sg[i] = v[i] > 0.f ? 1.f : (v[i] < 0.f ? -1.f : 0.f);

    float h[4][3];
#pragma unroll
    for (int j = 0; j < 3; ++j) {
        h[0][j] = sg[j];
        h[1][j] = 0.5f * (sg[j] + sg[3 + j] + sg[6 + j]);
        h[2][j] = 0.5f * (sg[j] - sg[3 + j] + sg[6 + j]);
        h[3][j] = sg[6 + j];
    }
    const int nh = oc >> 7, ocl = oc & 127;
#pragma unroll
    for (int r = 0; r < 4; ++r) {
        float a = h[r][0], bb = h[r][1], cc = h[r][2];
        float uu[4] = {a, 0.5f * (a + bb + cc), 0.5f * (a - bb + cc), cc};
#pragma unroll
        for (int q = 0; q < 4; ++q) {
            const int p = r * 4 + q;
            g_U[((size_t)(nh * 16 + p) * 128 + ocl) * AP + c] =
                (unsigned char)__nv_cvt_float_to_fp8(uu[q], __NV_SATFINITE, __NV_E4M3);
        }
    }
}

// ----------------------------------- input transform V = Bt d B -> e4m3
// mb = (b*64 + trow)*2 + chf ; tiles tcol = chf*32 + tloc
__global__ void __launch_bounds__(256) vtrans_kernel() {
    const int mb = blockIdx.x;                 // 0..1023
    const int b = mb >> 7, rr = mb & 127;
    const int trow = rr >> 1, chf = rr & 1;
    const int tid = threadIdx.x;
    const int c4 = (tid & 31) * 4;

    for (int tt = 0; tt < 4; ++tt) {
        const int tloc = (tid >> 5) * 4 + tt;
        const int tx = chf * 32 + tloc;
        uint32_t dw[16];
#pragma unroll
        for (int r = 0; r < 4; ++r)
#pragma unroll
            for (int cx = 0; cx < 4; ++cx)
                dw[r * 4 + cx] = __ldg(reinterpret_cast<const uint32_t*>(
                    g_act + ((size_t)((b * HPAD + 2 * trow + r) * HPAD) + 2 * tx + cx) * CINC + c4));

        uint32_t outp[16];
#pragma unroll
        for (int p = 0; p < 16; ++p) outp[p] = 0u;

#pragma unroll
        for (int ch = 0; ch < 4; ++ch) {
            int d[16];
#pragma unroll
            for (int i = 0; i < 16; ++i)
                d[i] = (int)(signed char)((dw[i] >> (8 * ch)) & 0xff);
            int e[16];
#pragma unroll
            for (int cx = 0; cx < 4; ++cx) {
                e[cx]      = d[cx] - d[8 + cx];
                e[4 + cx]  = d[4 + cx] + d[8 + cx];
                e[8 + cx]  = d[8 + cx] - d[4 + cx];
                e[12 + cx] = d[4 + cx] - d[12 + cx];
            }
#pragma unroll
            for (int r = 0; r < 4; ++r) {
                const int bs = r * 4;
                outp[bs]     |= e4m3_int(e[bs] - e[bs + 2])     << (8 * ch);
                outp[bs + 1] |= e4m3_int(e[bs + 1] + e[bs + 2]) << (8 * ch);
                outp[bs + 2] |= e4m3_int(e[bs + 2] - e[bs + 1]) << (8 * ch);
                outp[bs + 3] |= e4m3_int(e[bs + 1] - e[bs + 3]) << (8 * ch);
            }
        }
#pragma unroll
        for (int p = 0; p < 16; ++p)
            *reinterpret_cast<uint32_t*>(
                g_V + ((size_t)(mb * 16 + p) * 32 + tloc) * AP + c4) = outp[p];
    }
}

// ---------------------------------------------------------------- GEMM + fold
#define V_CHK  9216                          // 2 pos x 32 tiles x 144
#define U_CHK  36864                         // 2 pos x 128 oc x 144
#define CHK    (V_CHK + U_CHK)               // 46080
#define BAR_OFF (2 * CHK)                    // 92160
#define SMEM_TOT (BAR_OFF + 64)

__constant__ int c_S0[4] = {1, 1, 1, 0};
__constant__ int c_S1[4] = {0, 1, -1, -1};

__global__ void __launch_bounds__(512, 2) gemm_kernel(
    float* __restrict__ out,
    const float* __restrict__ pb0, const float* __restrict__ alpha,
    const float* __restrict__ pb1)
{
    extern __shared__ char smem[];
    const int nh = blockIdx.x;                // oc half
    const int mb = blockIdx.y;                // 32-tile block
    const int tid = threadIdx.x, lane = tid & 31, w = tid >> 5;
    const int wm = w >> 3, wn = w & 7;        // 2(M) x 8(N, n16 each)

    const uint32_t sbase = (uint32_t)__cvta_generic_to_shared(smem);
    const uint32_t FULL0 = sbase + BAR_OFF, FULL1 = sbase + BAR_OFF + 8;
    const uint32_t EMPT0 = sbase + BAR_OFF + 16, EMPT1 = sbase + BAR_OFF + 24;

    if (tid == 0) {
        mbar_init(FULL0, 1); mbar_init(FULL1, 1);
        mbar_init(EMPT0, 512); mbar_init(EMPT1, 512);
    }
    __syncthreads();

    const unsigned char* vsrc = g_V + (size_t)mb * (16 * 32 * AP);
    const unsigned char* usrc = g_U + (size_t)nh * (16 * 128 * AP);

    if (tid == 0) {
        mbar_expect(FULL0, CHK);
        bulkcp(sbase, vsrc, V_CHK, FULL0);
        bulkcp(sbase + V_CHK, usrc, U_CHK, FULL0);
        mbar_expect(FULL1, CHK);
        bulkcp(sbase + CHK, vsrc + V_CHK, V_CHK, FULL1);
        bulkcp(sbase + CHK + V_CHK, usrc + U_CHK, U_CHK, FULL1);
    }

    float y[2][4][4];                          // [nt][j][out00,01,10,11]
#pragma unroll
    for (int nt = 0; nt < 2; ++nt)
#pragma unroll
        for (int j = 0; j < 4; ++j)
#pragma unroll
            for (int o = 0; o < 4; ++o) y[nt][j][o] = 0.f;

    // validated fragment addressing
    const int lrow = lane & 7, grp = lane >> 3;
    const uint32_t laneA = (uint32_t)((wm * 16 + (grp & 1) * 8 + lrow) * AP + (grp >> 1) * 16);
    const uint32_t laneB = (uint32_t)((wn * 16 + (grp >> 1) * 8 + lrow) * AP + (grp & 1) * 16);

#pragma unroll
    for (int g = 0; g < 8; ++g) {
        mbar_wait((g & 1) ? FULL1 : FULL0, (g >> 1) & 1);
        const uint32_t vb = sbase + (g & 1) * CHK;
        const uint32_t ub = vb + V_CHK;

#pragma unroll
        for (int pp = 0; pp < 2; ++pp) {       // position p = 2g + pp
            const int p = 2 * g + pp;
            float acc[2][4];
#pragma unroll
            for (int nt = 0; nt < 2; ++nt)
#pragma unroll
                for (int j = 0; j < 4; ++j) acc[nt][j] = 0.f;

#pragma unroll
            for (int k0 = 0; k0 < 4; ++k0) {
                uint32_t a[4], r0, r1, r2, r3;
                ldsm4(a[0], a[1], a[2], a[3], vb + pp * (32 * AP) + laneA + k0 * 32);
                ldsm4(r0, r1, r2, r3, ub + pp * (128 * AP) + laneB + k0 * 32);
                uint32_t b01[2] = {r0, r1}, b23[2] = {r2, r3};
                mma16832f8(acc[0], a, b01);
                mma16832f8(acc[1], a, b23);
            }

            // fold position p into y (At x At coefficients, all 0/+-1)
            const int pr = p >> 2, pc = p & 3;
            const int s0r = c_S0[pr], s1r = c_S1[pr];
            const int s0c = c_S0[pc], s1c = c_S1[pc];
#pragma unroll
            for (int nt = 0; nt < 2; ++nt)
#pragma unroll
                for (int j = 0; j < 4; ++j) {
                    const float m = acc[nt][j];
                    if (s0r * s0c) y[nt][j][0] += (s0r * s0c > 0) ? m : -m;
                    if (s0r * s1c) y[nt][j][1] += (s0r * s1c > 0) ? m : -m;
                    if (s1r * s0c) y[nt][j][2] += (s1r * s0c > 0) ? m : -m;
                    if (s1r * s1c) y[nt][j][3] += (s1r * s1c > 0) ? m : -m;
                }
        }

        if (g < 6) {
            mbar_arrive((g & 1) ? EMPT1 : EMPT0);
            if (tid == 0) {
                mbar_wait((g & 1) ? EMPT1 : EMPT0, (g >> 1) & 1);
                mbar_expect((g & 1) ? FULL1 : FULL0, CHK);
                const uint32_t db = sbase + (g & 1) * CHK;
                bulkcp(db, vsrc + (size_t)(g + 2) * V_CHK, V_CHK,
                       (g & 1) ? FULL1 : FULL0);
                bulkcp(db + V_CHK, usrc + (size_t)(g + 2) * U_CHK, U_CHK,
                       (g & 1) ? FULL1 : FULL0);
            }
        }
    }

    // --- epilogue: scale/bias/PReLU/bias + store 2x2 tile outputs ---
    const int b = mb >> 7, rr = mb & 127;
    const int trow = rr >> 1, chf = rr & 1;

#pragma unroll
    for (int nt = 0; nt < 2; ++nt)
#pragma unroll
    for (int j = 0; j < 4; ++j) {
        const int tloc = wm * 16 + (lane >> 2) + (j >> 1) * 8;
        const int oc = nh * 128 + wn * 16 + nt * 8 + (lane & 3) * 2 + (j & 1);
        const float sc = g_wscale[oc];
        const float c0 = __ldg(pb0 + oc);
        const float al = __ldg(alpha + oc);
        const float d1 = __ldg(pb1 + oc);

        const int tcol = chf * 32 + tloc;
        float* op = out + (((size_t)(b * COC + oc) * 128 + 2 * trow) * 128 + 2 * tcol);
        float v;
        float2 o0, o1;
        v = y[nt][j][0] * sc + c0; v = v >= 0.f ? v : v * al; o0.x = v + d1;
        v = y[nt][j][1] * sc + c0; v = v >= 0.f ? v : v * al; o0.y = v + d1;
        v = y[nt][j][2] * sc + c0; v = v >= 0.f ? v : v * al; o1.x = v + d1;
        v = y[nt][j][3] * sc + c0; v = v >= 0.f ? v : v * al; o1.y = v + d1;
        *reinterpret_cast<float2*>(op) = o0;
        *reinterpret_cast<float2*>(op + 128) = o1;
    }
}

// ---------------------------------------------------------------- launcher
extern "C" void kernel_launch(void* const* d_in, const int* in_sizes, int n_in,
                              void* d_out, int out_size) {
    const float* x   = (const float*)d_in[0];
    const float* wt  = (const float*)d_in[1];
    const float* mb  = (const float*)d_in[2];
    const float* pb0 = (const float*)d_in[3];
    const float* al  = (const float*)d_in[4];
    const float* pb1 = (const float*)d_in[5];
    float* out = (float*)d_out;

    cudaFuncSetAttribute(gemm_kernel, cudaFuncAttributeMaxDynamicSharedMemorySize, SMEM_TOT);

    prep_kernel<<<dim3(128, NB), 256>>>(x, mb);
    wprep_kernel<<<COC, 128>>>(wt);
    vtrans_kernel<<<NMB, 256>>>();
    gemm_kernel<<<dim3(2, NMB), 512, SMEM_TOT>>>(out, pb0, al, pb1);
}

// round 15
// speedup vs baseline: 1.2369x; 1.1205x over previous
#include <cuda_runtime.h>
#include <cuda_fp8.h>
#include <cstdint>
#include <cmath>

// ---------------------------------------------------------------------------
// BinaryConv2dBBCU_Down via Winograd F(2x2,3x3), all-exact arithmetic, as a
// SINGLE fused pipeline kernel: wprep + per-image [prep -> vtrans -> gemm]
// with monotone flag dependencies (validated R12 pattern), overlapping the
// DRAM-bound prep / latency-bound vtrans under the tensor-bound gemm.
// ---------------------------------------------------------------------------

#define NB   8
#define CINC 128
#define COC  256
#define HPAD 130
#define AP   144
#define NMB  1024                    // 32-tile M-blocks (32768 tiles total)

// device scratch
__device__ __align__(256) signed char   g_act[(size_t)NB * HPAD * HPAD * CINC];
__device__ __align__(256) unsigned char g_V[(size_t)NMB * 16 * 32 * AP];   // [mb][pos][tile32][144]
__device__ __align__(256) unsigned char g_U[(size_t)2 * 16 * 128 * AP];    // [nh][pos][oc128][144]
__device__ float g_wscale[COC];
__device__ int   g_rowflag[NB][128];   // zero-init, monotone
__device__ int   g_vflag[NMB];         // zero-init, monotone
__device__ int   g_wcnt[2];            // monotone; ==128 => U half ready

// ------------------------------------------------------------- PTX helpers
__device__ __forceinline__ void bulkcp(uint32_t dst, const void* src, uint32_t bytes,
                                       uint32_t mbar) {
    asm volatile("cp.async.bulk.shared::cta.global.mbarrier::complete_tx::bytes "
                 "[%0], [%1], %2, [%3];"
                 :: "r"(dst), "l"(src), "r"(bytes), "r"(mbar) : "memory");
}
__device__ __forceinline__ void mbar_init(uint32_t a, uint32_t cnt) {
    asm volatile("mbarrier.init.shared.b64 [%0], %1;" :: "r"(a), "r"(cnt) : "memory");
}
__device__ __forceinline__ void mbar_expect(uint32_t a, uint32_t bytes) {
    asm volatile("mbarrier.arrive.expect_tx.shared.b64 _, [%0], %1;"
                 :: "r"(a), "r"(bytes) : "memory");
}
__device__ __forceinline__ void mbar_arrive(uint32_t a) {
    asm volatile("mbarrier.arrive.shared.b64 _, [%0];" :: "r"(a) : "memory");
}
__device__ __forceinline__ void mbar_wait(uint32_t a, uint32_t parity) {
    asm volatile(
        "{\n\t.reg .pred P1;\n\t"
        "WAIT_%=:\n\t"
        "mbarrier.try_wait.parity.acquire.cta.shared::cta.b64 P1, [%0], %1, 0x989680;\n\t"
        "@P1 bra.uni DONE_%=;\n\t"
        "bra.uni WAIT_%=;\n\t"
        "DONE_%=:\n\t}"
        :: "r"(a), "r"(parity) : "memory");
}
__device__ __forceinline__ int ld_acq(const int* p) {
    int v;
    asm volatile("ld.global.acquire.gpu.b32 %0, [%1];" : "=r"(v) : "l"(p) : "memory");
    return v;
}
__device__ __forceinline__ void ldsm4(uint32_t& r0, uint32_t& r1, uint32_t& r2, uint32_t& r3,
                                      uint32_t a) {
    asm volatile("ldmatrix.sync.aligned.m8n8.x4.shared.b16 {%0,%1,%2,%3},[%4];\n"
                 : "=r"(r0), "=r"(r1), "=r"(r2), "=r"(r3) : "r"(a));
}
__device__ __forceinline__ void mma16832f8(float* c, const uint32_t* a, const uint32_t* b) {
    asm volatile("mma.sync.aligned.m16n8k32.row.col.f32.e4m3.e4m3.f32 "
                 "{%0,%1,%2,%3},{%4,%5,%6,%7},{%8,%9},{%0,%1,%2,%3};\n"
                 : "+f"(c[0]), "+f"(c[1]), "+f"(c[2]), "+f"(c[3])
                 : "r"(a[0]), "r"(a[1]), "r"(a[2]), "r"(a[3]), "r"(b[0]), "r"(b[1]));
}
__device__ __forceinline__ uint32_t e4m3_int(int v) {
    int a = v < 0 ? -v : v;
    uint32_t mag = a ? ((0x48444038u >> (8 * (a - 1))) & 0xffu) : 0u;
    return v < 0 ? (mag | 0x80u) : mag;
}

// GEMM smem layout
#define V_CHK  9216                          // 2 pos x 32 tiles x 144
#define U_CHK  36864                         // 2 pos x 128 oc x 144
#define CHK    (V_CHK + U_CHK)               // 46080
#define BAR_OFF (2 * CHK)                    // 92160
#define SMEM_TOT (BAR_OFF + 64)              // 92224 -> 2 CTAs/SM

__constant__ int c_S0[4] = {1, 1, 1, 0};
__constant__ int c_S1[4] = {0, 1, -1, -1};

// ---------------------------------------------------------------- pipeline
// grid: [0,64)                          wprep (4 oc per block)
//       64 + b*512 + [0,128)            prep   image b, pooled row y
//       64 + b*512 + 128 + [0,128)      vtrans image b, rr (trow,chf)
//       64 + b*512 + 256 + [0,256)      gemm   image b, nh*128 + rr
__global__ void __launch_bounds__(512, 2) fused_kernel(
    const float* __restrict__ x, const float* __restrict__ wt,
    const float* __restrict__ mbias,
    float* __restrict__ out,
    const float* __restrict__ pb0, const float* __restrict__ alpha,
    const float* __restrict__ pb1)
{
    extern __shared__ char smem[];
    const int bid = blockIdx.x;
    const int tid = threadIdx.x, lane = tid & 31;

    // ================================================================ wprep
    if (bid < 64) {
        const int oc = bid * 4 + (tid >> 7);
        const int c = tid & 127;
        const float* wp = wt + ((size_t)oc * CINC + c) * 9;
        float v[9]; float s = 0.f;
#pragma unroll
        for (int i = 0; i < 9; ++i) { v[i] = wp[i]; s += fabsf(v[i]); }

        float* red = reinterpret_cast<float*>(smem);
        red[tid] = s;
        __syncthreads();
        for (int o = 64; o > 0; o >>= 1) {
            if (c < o) red[tid] += red[tid + o];
            __syncthreads();
        }
        if (c == 0) g_wscale[oc] = red[tid] * (1.f / 1152.f);

        float sg[9];
#pragma unroll
        for (int i = 0; i < 9; ++i) sg[i] = v[i] > 0.f ? 1.f : (v[i] < 0.f ? -1.f : 0.f);
        float h[4][3];
#pragma unroll
        for (int j = 0; j < 3; ++j) {
            h[0][j] = sg[j];
            h[1][j] = 0.5f * (sg[j] + sg[3 + j] + sg[6 + j]);
            h[2][j] = 0.5f * (sg[j] - sg[3 + j] + sg[6 + j]);
            h[3][j] = sg[6 + j];
        }
        const int nh = oc >> 7, ocl = oc & 127;
#pragma unroll
        for (int r = 0; r < 4; ++r) {
            float a = h[r][0], bb = h[r][1], cc = h[r][2];
            float uu[4] = {a, 0.5f * (a + bb + cc), 0.5f * (a - bb + cc), cc};
#pragma unroll
            for (int q = 0; q < 4; ++q) {
                const int p = r * 4 + q;
                g_U[((size_t)(nh * 16 + p) * 128 + ocl) * AP + c] =
                    (unsigned char)__nv_cvt_float_to_fp8(uu[q], __NV_SATFINITE, __NV_E4M3);
            }
        }
        __threadfence();
        if (c == 0) atomicAdd(&g_wcnt[nh], 1);
        return;
    }

    const int seg = bid - 64;
    const int b = seg >> 9;
    const int off = seg & 511;

    // ================================================================= prep
    if (off < 128) {
        const int y = off;
        const int wrp = tid >> 5;
        signed char* st = reinterpret_cast<signed char*>(smem);   // [x][c] pitch 136

        for (int k = 0; k < 8; ++k) {
            const int c = wrp + 16 * k;
            const float* r0 = x + ((size_t)(b * CINC + c) * 256 + 2 * y) * 256;
            const float* r1 = r0 + 256;
            const float bias = __ldg(mbias + c);
#pragma unroll
            for (int xb = 0; xb < 2; ++xb) {
                const int xo = xb * 64 + lane * 2;
                float4 u = *reinterpret_cast<const float4*>(r0 + 2 * xo);
                float4 v = *reinterpret_cast<const float4*>(r1 + 2 * xo);
                float p0 = (u.x + u.y + v.x + v.y) * 0.25f + bias;
                float p1 = (u.z + u.w + v.z + v.w) * 0.25f + bias;
                st[xo * 136 + c]       = p0 > 0.f ? 1 : (p0 < 0.f ? -1 : 0);
                st[(xo + 1) * 136 + c] = p1 > 0.f ? 1 : (p1 < 0.f ? -1 : 0);
            }
        }
        __syncthreads();

        uint32_t* dst = reinterpret_cast<uint32_t*>(
            g_act + ((size_t)(b * HPAD + (y + 1)) * HPAD) * CINC);
        const char* sp = reinterpret_cast<const char*>(st);
        for (int i = tid; i < 128 * 32; i += 512) {
            const int xr = i >> 5, wd = i & 31;
            dst[(xr + 1) * 32 + wd] = *reinterpret_cast<const uint32_t*>(sp + xr * 136 + wd * 4);
        }

        uint32_t* base = reinterpret_cast<uint32_t*>(g_act + ((size_t)b * HPAD * HPAD) * CINC);
        if (y == 0) {
            for (int i = tid; i < HPAD * 32; i += 512) base[i] = 0u;
        } else if (y == 127) {
            uint32_t* r129 = base + (size_t)129 * HPAD * 32;
            for (int i = tid; i < HPAD * 32; i += 512) r129[i] = 0u;
        }
        uint32_t* rowp = base + (size_t)(y + 1) * HPAD * 32;
        if (tid < 32) rowp[tid] = 0u;
        else if (tid < 64) rowp[129 * 32 + (tid - 32)] = 0u;

        __threadfence();
        __syncthreads();
        if (tid == 0) atomicExch(&g_rowflag[b][y], 1);
        return;
    }

    // ================================================================ vtrans
    if (off < 256) {
        const int rr = off - 128;
        const int mb = b * 128 + rr;
        const int trow = rr >> 1, chf = rr & 1;
        const int c4 = (tid & 31) * 4;
        const int w = tid >> 5;

        if (tid == 0) {
            const int ylo = trow > 0 ? 2 * trow - 1 : 0;
            while (ld_acq(&g_rowflag[b][ylo]) == 0) __nanosleep(64);
            while (ld_acq(&g_rowflag[b][2 * trow]) == 0) __nanosleep(64);
            while (ld_acq(&g_rowflag[b][2 * trow + 1]) == 0) __nanosleep(64);
            if (trow < 63)
                while (ld_acq(&g_rowflag[b][2 * trow + 2]) == 0) __nanosleep(64);
        }
        __syncthreads();

        for (int tt = 0; tt < 2; ++tt) {
            const int tloc = w * 2 + tt;
            const int tx = chf * 32 + tloc;
            uint32_t dw[16];
#pragma unroll
            for (int r = 0; r < 4; ++r)
#pragma unroll
                for (int cx = 0; cx < 4; ++cx)
                    dw[r * 4 + cx] = __ldg(reinterpret_cast<const uint32_t*>(
                        g_act + ((size_t)((b * HPAD + 2 * trow + r) * HPAD) + 2 * tx + cx) * CINC + c4));

            uint32_t outp[16];
#pragma unroll
            for (int p = 0; p < 16; ++p) outp[p] = 0u;

#pragma unroll
            for (int ch = 0; ch < 4; ++ch) {
                int d[16];
#pragma unroll
                for (int i = 0; i < 16; ++i)
                    d[i] = (int)(signed char)((dw[i] >> (8 * ch)) & 0xff);
                int e[16];
#pragma unroll
                for (int cx = 0; cx < 4; ++cx) {
                    e[cx]      = d[cx] - d[8 + cx];
                    e[4 + cx]  = d[4 + cx] + d[8 + cx];
                    e[8 + cx]  = d[8 + cx] - d[4 + cx];
                    e[12 + cx] = d[4 + cx] - d[12 + cx];
                }
#pragma unroll
                for (int r = 0; r < 4; ++r) {
                    const int bs = r * 4;
                    outp[bs]     |= e4m3_int(e[bs] - e[bs + 2])     << (8 * ch);
                    outp[bs + 1] |= e4m3_int(e[bs + 1] + e[bs + 2]) << (8 * ch);
                    outp[bs + 2] |= e4m3_int(e[bs + 2] - e[bs + 1]) << (8 * ch);
                    outp[bs + 3] |= e4m3_int(e[bs + 1] - e[bs + 3]) << (8 * ch);
                }
            }
#pragma unroll
            for (int p = 0; p < 16; ++p)
                *reinterpret_cast<uint32_t*>(
                    g_V + ((size_t)(mb * 16 + p) * 32 + tloc) * AP + c4) = outp[p];
        }

        __threadfence();
        __syncthreads();
        if (tid == 0) atomicExch(&g_vflag[mb], 1);
        return;
    }

    // ================================================================== gemm
    const int cid = off - 256;
    const int nh = cid >> 7;
    const int mb = b * 128 + (cid & 127);
    const int w = tid >> 5;
    const int wm = w >> 3, wn = w & 7;

    const uint32_t sbase = (uint32_t)__cvta_generic_to_shared(smem);
    const uint32_t FULL0 = sbase + BAR_OFF, FULL1 = sbase + BAR_OFF + 8;
    const uint32_t EMPT0 = sbase + BAR_OFF + 16, EMPT1 = sbase + BAR_OFF + 24;

    if (tid == 0) {
        mbar_init(FULL0, 1); mbar_init(FULL1, 1);
        mbar_init(EMPT0, 512); mbar_init(EMPT1, 512);
    }
    __syncthreads();

    const unsigned char* vsrc = g_V + (size_t)mb * (16 * 32 * AP);
    const unsigned char* usrc = g_U + (size_t)nh * (16 * 128 * AP);

    if (tid == 0) {
        while (ld_acq(&g_wcnt[nh]) < 128) __nanosleep(64);
        while (ld_acq(&g_vflag[mb]) == 0) __nanosleep(64);
        asm volatile("fence.proxy.async;" ::: "memory");
        mbar_expect(FULL0, CHK);
        bulkcp(sbase, vsrc, V_CHK, FULL0);
        bulkcp(sbase + V_CHK, usrc, U_CHK, FULL0);
        mbar_expect(FULL1, CHK);
        bulkcp(sbase + CHK, vsrc + V_CHK, V_CHK, FULL1);
        bulkcp(sbase + CHK + V_CHK, usrc + U_CHK, U_CHK, FULL1);
    }

    float y[2][4][4];
#pragma unroll
    for (int nt = 0; nt < 2; ++nt)
#pragma unroll
        for (int j = 0; j < 4; ++j)
#pragma unroll
            for (int o = 0; o < 4; ++o) y[nt][j][o] = 0.f;

    const int lrow = lane & 7, grp = lane >> 3;
    const uint32_t laneA = (uint32_t)((wm * 16 + (grp & 1) * 8 + lrow) * AP + (grp >> 1) * 16);
    const uint32_t laneB = (uint32_t)((wn * 16 + (grp >> 1) * 8 + lrow) * AP + (grp & 1) * 16);

#pragma unroll
    for (int g = 0; g < 8; ++g) {
        mbar_wait((g & 1) ? FULL1 : FULL0, (g >> 1) & 1);
        const uint32_t vb = sbase + (g & 1) * CHK;
        const uint32_t ub = vb + V_CHK;

#pragma unroll
        for (int pp = 0; pp < 2; ++pp) {
            const int p = 2 * g + pp;
            float acc[2][4];
#pragma unroll
            for (int nt = 0; nt < 2; ++nt)
#pragma unroll
                for (int j = 0; j < 4; ++j) acc[nt][j] = 0.f;

#pragma unroll
            for (int k0 = 0; k0 < 4; ++k0) {
                uint32_t a[4], r0, r1, r2, r3;
                ldsm4(a[0], a[1], a[2], a[3], vb + pp * (32 * AP) + laneA + k0 * 32);
                ldsm4(r0, r1, r2, r3, ub + pp * (128 * AP) + laneB + k0 * 32);
                uint32_t b01[2] = {r0, r1}, b23[2] = {r2, r3};
                mma16832f8(acc[0], a, b01);
                mma16832f8(acc[1], a, b23);
            }

            const int pr = p >> 2, pc = p & 3;
            const int s0r = c_S0[pr], s1r = c_S1[pr];
            const int s0c = c_S0[pc], s1c = c_S1[pc];
#pragma unroll
            for (int nt = 0; nt < 2; ++nt)
#pragma unroll
                for (int j = 0; j < 4; ++j) {
                    const float m = acc[nt][j];
                    if (s0r * s0c) y[nt][j][0] += (s0r * s0c > 0) ? m : -m;
                    if (s0r * s1c) y[nt][j][1] += (s0r * s1c > 0) ? m : -m;
                    if (s1r * s0c) y[nt][j][2] += (s1r * s0c > 0) ? m : -m;
                    if (s1r * s1c) y[nt][j][3] += (s1r * s1c > 0) ? m : -m;
                }
        }

        if (g < 6) {
            mbar_arrive((g & 1) ? EMPT1 : EMPT0);
            if (tid == 0) {
                mbar_wait((g & 1) ? EMPT1 : EMPT0, (g >> 1) & 1);
                mbar_expect((g & 1) ? FULL1 : FULL0, CHK);
                const uint32_t db = sbase + (g & 1) * CHK;
                bulkcp(db, vsrc + (size_t)(g + 2) * V_CHK, V_CHK,
                       (g & 1) ? FULL1 : FULL0);
                bulkcp(db + V_CHK, usrc + (size_t)(g + 2) * U_CHK, U_CHK,
                       (g & 1) ? FULL1 : FULL0);
            }
        }
    }

    // --- epilogue ---
    const int rr = mb & 127;
    const int trow = rr >> 1, chf = rr & 1;

#pragma unroll
    for (int nt = 0; nt < 2; ++nt)
#pragma unroll
    for (int j = 0; j < 4; ++j) {
        const int tloc = wm * 16 + (lane >> 2) + (j >> 1) * 8;
        const int oc = nh * 128 + wn * 16 + nt * 8 + (lane & 3) * 2 + (j & 1);
        const float sc = g_wscale[oc];
        const float c0 = __ldg(pb0 + oc);
        const float al = __ldg(alpha + oc);
        const float d1 = __ldg(pb1 + oc);

        const int tcol = chf * 32 + tloc;
        float* op = out + (((size_t)(b * COC + oc) * 128 + 2 * trow) * 128 + 2 * tcol);
        float v;
        float2 o0, o1;
        v = y[nt][j][0] * sc + c0; v = v >= 0.f ? v : v * al; o0.x = v + d1;
        v = y[nt][j][1] * sc + c0; v = v >= 0.f ? v : v * al; o0.y = v + d1;
        v = y[nt][j][2] * sc + c0; v = v >= 0.f ? v : v * al; o1.x = v + d1;
        v = y[nt][j][3] * sc + c0; v = v >= 0.f ? v : v * al; o1.y = v + d1;
        *reinterpret_cast<float2*>(op) = o0;
        *reinterpret_cast<float2*>(op + 128) = o1;
    }
}

// ---------------------------------------------------------------- launcher
extern "C" void kernel_launch(void* const* d_in, const int* in_sizes, int n_in,
                              void* d_out, int out_size) {
    const float* x   = (const float*)d_in[0];
    const float* wt  = (const float*)d_in[1];
    const float* mb  = (const float*)d_in[2];
    const float* pb0 = (const float*)d_in[3];
    const float* al  = (const float*)d_in[4];
    const float* pb1 = (const float*)d_in[5];
    float* out = (float*)d_out;

    cudaFuncSetAttribute(fused_kernel, cudaFuncAttributeMaxDynamicSharedMemorySize, SMEM_TOT);

    // 64 wprep + 8 * (128 prep + 128 vtrans + 256 gemm) = 4160 blocks
    fused_kernel<<<4160, 512, SMEM_TOT>>>(x, wt, mb, out, pb0, al, pb1);
}

// round 16
// speedup vs baseline: 1.2702x; 1.0269x over previous
#include <cuda_runtime.h>
#include <cuda_fp8.h>
#include <cstdint>
#include <cmath>

// ---------------------------------------------------------------------------
// BinaryConv2dBBCU_Down via Winograd F(2x2,3x3), all-exact arithmetic, as a
// SINGLE fused pipeline kernel: wprep + per-image [prep -> vtrans -> gemm]
// with monotone flag dependencies. vtrans is SIMD-within-register: the
// Bt d B network runs on packed 4-channel bytes (vadd4/vsub4) and e4m3
// encoding is a PRMT table lookup -- ~4.8x fewer ALU ops than scalar.
// ---------------------------------------------------------------------------

#define NB   8
#define CINC 128
#define COC  256
#define HPAD 130
#define AP   144
#define NMB  1024                    // 32-tile M-blocks (32768 tiles total)

// device scratch
__device__ __align__(256) signed char   g_act[(size_t)NB * HPAD * HPAD * CINC];
__device__ __align__(256) unsigned char g_V[(size_t)NMB * 16 * 32 * AP];   // [mb][pos][tile32][144]
__device__ __align__(256) unsigned char g_U[(size_t)2 * 16 * 128 * AP];    // [nh][pos][oc128][144]
__device__ float g_wscale[COC];
__device__ int   g_rowflag[NB][128];   // zero-init, monotone
__device__ int   g_vflag[NMB];         // zero-init, monotone
__device__ int   g_wcnt[2];            // monotone; ==128 => U half ready

// ------------------------------------------------------------- PTX helpers
__device__ __forceinline__ void bulkcp(uint32_t dst, const void* src, uint32_t bytes,
                                       uint32_t mbar) {
    asm volatile("cp.async.bulk.shared::cta.global.mbarrier::complete_tx::bytes "
                 "[%0], [%1], %2, [%3];"
                 :: "r"(dst), "l"(src), "r"(bytes), "r"(mbar) : "memory");
}
__device__ __forceinline__ void mbar_init(uint32_t a, uint32_t cnt) {
    asm volatile("mbarrier.init.shared.b64 [%0], %1;" :: "r"(a), "r"(cnt) : "memory");
}
__device__ __forceinline__ void mbar_expect(uint32_t a, uint32_t bytes) {
    asm volatile("mbarrier.arrive.expect_tx.shared.b64 _, [%0], %1;"
                 :: "r"(a), "r"(bytes) : "memory");
}
__device__ __forceinline__ void mbar_arrive(uint32_t a) {
    asm volatile("mbarrier.arrive.shared.b64 _, [%0];" :: "r"(a) : "memory");
}
__device__ __forceinline__ void mbar_wait(uint32_t a, uint32_t parity) {
    asm volatile(
        "{\n\t.reg .pred P1;\n\t"
        "WAIT_%=:\n\t"
        "mbarrier.try_wait.parity.acquire.cta.shared::cta.b64 P1, [%0], %1, 0x989680;\n\t"
        "@P1 bra.uni DONE_%=;\n\t"
        "bra.uni WAIT_%=;\n\t"
        "DONE_%=:\n\t}"
        :: "r"(a), "r"(parity) : "memory");
}
__device__ __forceinline__ int ld_acq(const int* p) {
    int v;
    asm volatile("ld.global.acquire.gpu.b32 %0, [%1];" : "=r"(v) : "l"(p) : "memory");
    return v;
}
__device__ __forceinline__ void ldsm4(uint32_t& r0, uint32_t& r1, uint32_t& r2, uint32_t& r3,
                                      uint32_t a) {
    asm volatile("ldmatrix.sync.aligned.m8n8.x4.shared.b16 {%0,%1,%2,%3},[%4];\n"
                 : "=r"(r0), "=r"(r1), "=r"(r2), "=r"(r3) : "r"(a));
}
__device__ __forceinline__ void mma16832f8(float* c, const uint32_t* a, const uint32_t* b) {
    asm volatile("mma.sync.aligned.m16n8k32.row.col.f32.e4m3.e4m3.f32 "
                 "{%0,%1,%2,%3},{%4,%5,%6,%7},{%8,%9},{%0,%1,%2,%3};\n"
                 : "+f"(c[0]), "+f"(c[1]), "+f"(c[2]), "+f"(c[3])
                 : "r"(a[0]), "r"(a[1]), "r"(a[2]), "r"(a[3]), "r"(b[0]), "r"(b[1]));
}
// packed e4m3 encode: 4 int8 values in [-4,4] -> 4 e4m3 bytes (exact)
__device__ __forceinline__ uint32_t e4m3_pack4(uint32_t v) {
    const uint32_t sgn = v & 0x80808080u;
    const uint32_t mag = __vabsss4(v);                 // bytes in 0..4
    const uint32_t sel = (mag & 0xFu) | ((mag >> 4) & 0xF0u) |
                         ((mag >> 8) & 0xF00u) | ((mag >> 12) & 0xF000u);
    return __byte_perm(0x44403800u, 0x48u, sel) | sgn; // {0,1,2,3,4}->{0,38,40,44,48}
}

// GEMM smem layout
#define V_CHK  9216                          // 2 pos x 32 tiles x 144
#define U_CHK  36864                         // 2 pos x 128 oc x 144
#define CHK    (V_CHK + U_CHK)               // 46080
#define BAR_OFF (2 * CHK)                    // 92160
#define SMEM_TOT (BAR_OFF + 64)              // 92224 -> 2 CTAs/SM

__constant__ int c_S0[4] = {1, 1, 1, 0};
__constant__ int c_S1[4] = {0, 1, -1, -1};

// ---------------------------------------------------------------- pipeline
// grid: [0,64)                          wprep (4 oc per block)
//       64 + b*512 + [0,128)            prep   image b, pooled row y
//       64 + b*512 + 128 + [0,128)      vtrans image b, rr (trow,chf)
//       64 + b*512 + 256 + [0,256)      gemm   image b, nh*128 + rr
__global__ void __launch_bounds__(512, 2) fused_kernel(
    const float* __restrict__ x, const float* __restrict__ wt,
    const float* __restrict__ mbias,
    float* __restrict__ out,
    const float* __restrict__ pb0, const float* __restrict__ alpha,
    const float* __restrict__ pb1)
{
    extern __shared__ char smem[];
    const int bid = blockIdx.x;
    const int tid = threadIdx.x, lane = tid & 31;

    // ================================================================ wprep
    if (bid < 64) {
        const int oc = bid * 4 + (tid >> 7);
        const int c = tid & 127;
        const float* wp = wt + ((size_t)oc * CINC + c) * 9;
        float v[9]; float s = 0.f;
#pragma unroll
        for (int i = 0; i < 9; ++i) { v[i] = wp[i]; s += fabsf(v[i]); }

        float* red = reinterpret_cast<float*>(smem);
        red[tid] = s;
        __syncthreads();
        for (int o = 64; o > 0; o >>= 1) {
            if (c < o) red[tid] += red[tid + o];
            __syncthreads();
        }
        if (c == 0) g_wscale[oc] = red[tid] * (1.f / 1152.f);

        float sg[9];
#pragma unroll
        for (int i = 0; i < 9; ++i) sg[i] = v[i] > 0.f ? 1.f : (v[i] < 0.f ? -1.f : 0.f);
        float h[4][3];
#pragma unroll
        for (int j = 0; j < 3; ++j) {
            h[0][j] = sg[j];
            h[1][j] = 0.5f * (sg[j] + sg[3 + j] + sg[6 + j]);
            h[2][j] = 0.5f * (sg[j] - sg[3 + j] + sg[6 + j]);
            h[3][j] = sg[6 + j];
        }
        const int nh = oc >> 7, ocl = oc & 127;
#pragma unroll
        for (int r = 0; r < 4; ++r) {
            float a = h[r][0], bb = h[r][1], cc = h[r][2];
            float uu[4] = {a, 0.5f * (a + bb + cc), 0.5f * (a - bb + cc), cc};
#pragma unroll
            for (int q = 0; q < 4; ++q) {
                const int p = r * 4 + q;
                g_U[((size_t)(nh * 16 + p) * 128 + ocl) * AP + c] =
                    (unsigned char)__nv_cvt_float_to_fp8(uu[q], __NV_SATFINITE, __NV_E4M3);
            }
        }
        __threadfence();
        if (c == 0) atomicAdd(&g_wcnt[nh], 1);
        return;
    }

    const int seg = bid - 64;
    const int b = seg >> 9;
    const int off = seg & 511;

    // ================================================================= prep
    if (off < 128) {
        const int y = off;
        const int wrp = tid >> 5;
        signed char* st = reinterpret_cast<signed char*>(smem);   // [x][c] pitch 136

        for (int k = 0; k < 8; ++k) {
            const int c = wrp + 16 * k;
            const float* r0 = x + ((size_t)(b * CINC + c) * 256 + 2 * y) * 256;
            const float* r1 = r0 + 256;
            const float bias = __ldg(mbias + c);
#pragma unroll
            for (int xb = 0; xb < 2; ++xb) {
                const int xo = xb * 64 + lane * 2;
                float4 u = *reinterpret_cast<const float4*>(r0 + 2 * xo);
                float4 v = *reinterpret_cast<const float4*>(r1 + 2 * xo);
                float p0 = (u.x + u.y + v.x + v.y) * 0.25f + bias;
                float p1 = (u.z + u.w + v.z + v.w) * 0.25f + bias;
                st[xo * 136 + c]       = p0 > 0.f ? 1 : (p0 < 0.f ? -1 : 0);
                st[(xo + 1) * 136 + c] = p1 > 0.f ? 1 : (p1 < 0.f ? -1 : 0);
            }
        }
        __syncthreads();

        uint32_t* dst = reinterpret_cast<uint32_t*>(
            g_act + ((size_t)(b * HPAD + (y + 1)) * HPAD) * CINC);
        const char* sp = reinterpret_cast<const char*>(st);
        for (int i = tid; i < 128 * 32; i += 512) {
            const int xr = i >> 5, wd = i & 31;
            dst[(xr + 1) * 32 + wd] = *reinterpret_cast<const uint32_t*>(sp + xr * 136 + wd * 4);
        }

        uint32_t* base = reinterpret_cast<uint32_t*>(g_act + ((size_t)b * HPAD * HPAD) * CINC);
        if (y == 0) {
            for (int i = tid; i < HPAD * 32; i += 512) base[i] = 0u;
        } else if (y == 127) {
            uint32_t* r129 = base + (size_t)129 * HPAD * 32;
            for (int i = tid; i < HPAD * 32; i += 512) r129[i] = 0u;
        }
        uint32_t* rowp = base + (size_t)(y + 1) * HPAD * 32;
        if (tid < 32) rowp[tid] = 0u;
        else if (tid < 64) rowp[129 * 32 + (tid - 32)] = 0u;

        __threadfence();
        __syncthreads();
        if (tid == 0) atomicExch(&g_rowflag[b][y], 1);
        return;
    }

    // ================================================================ vtrans
    if (off < 256) {
        const int rr = off - 128;
        const int mb = b * 128 + rr;
        const int trow = rr >> 1, chf = rr & 1;
        const int c4 = (tid & 31) * 4;
        const int w = tid >> 5;

        if (tid == 0) {
            const int ylo = trow > 0 ? 2 * trow - 1 : 0;
            while (ld_acq(&g_rowflag[b][ylo]) == 0) __nanosleep(64);
            while (ld_acq(&g_rowflag[b][2 * trow]) == 0) __nanosleep(64);
            while (ld_acq(&g_rowflag[b][2 * trow + 1]) == 0) __nanosleep(64);
            if (trow < 63)
                while (ld_acq(&g_rowflag[b][2 * trow + 2]) == 0) __nanosleep(64);
        }
        __syncthreads();

        for (int tt = 0; tt < 2; ++tt) {
            const int tloc = w * 2 + tt;
            const int tx = chf * 32 + tloc;
            uint32_t dw[16];
#pragma unroll
            for (int r = 0; r < 4; ++r)
#pragma unroll
                for (int cx = 0; cx < 4; ++cx)
                    dw[r * 4 + cx] = __ldg(reinterpret_cast<const uint32_t*>(
                        g_act + ((size_t)((b * HPAD + 2 * trow + r) * HPAD) + 2 * tx + cx) * CINC + c4));

            // packed Bt d B across 4 channels at once (values |<=4|, exact)
            uint32_t e[16];
#pragma unroll
            for (int cx = 0; cx < 4; ++cx) {
                e[cx]      = __vsub4(dw[cx],     dw[8 + cx]);
                e[4 + cx]  = __vadd4(dw[4 + cx], dw[8 + cx]);
                e[8 + cx]  = __vsub4(dw[8 + cx], dw[4 + cx]);
                e[12 + cx] = __vsub4(dw[4 + cx], dw[12 + cx]);
            }
            uint32_t outp[16];
#pragma unroll
            for (int r = 0; r < 4; ++r) {
                const int bs = r * 4;
                outp[bs]     = e4m3_pack4(__vsub4(e[bs],     e[bs + 2]));
                outp[bs + 1] = e4m3_pack4(__vadd4(e[bs + 1], e[bs + 2]));
                outp[bs + 2] = e4m3_pack4(__vsub4(e[bs + 2], e[bs + 1]));
                outp[bs + 3] = e4m3_pack4(__vsub4(e[bs + 1], e[bs + 3]));
            }
#pragma unroll
            for (int p = 0; p < 16; ++p)
                *reinterpret_cast<uint32_t*>(
                    g_V + ((size_t)(mb * 16 + p) * 32 + tloc) * AP + c4) = outp[p];
        }

        __threadfence();
        __syncthreads();
        if (tid == 0) atomicExch(&g_vflag[mb], 1);
        return;
    }

    // ================================================================== gemm
    const int cid = off - 256;
    const int nh = cid >> 7;
    const int mb = b * 128 + (cid & 127);
    const int w = tid >> 5;
    const int wm = w >> 3, wn = w & 7;

    const uint32_t sbase = (uint32_t)__cvta_generic_to_shared(smem);
    const uint32_t FULL0 = sbase + BAR_OFF, FULL1 = sbase + BAR_OFF + 8;
    const uint32_t EMPT0 = sbase + BAR_OFF + 16, EMPT1 = sbase + BAR_OFF + 24;

    if (tid == 0) {
        mbar_init(FULL0, 1); mbar_init(FULL1, 1);
        mbar_init(EMPT0, 512); mbar_init(EMPT1, 512);
    }
    __syncthreads();

    const unsigned char* vsrc = g_V + (size_t)mb * (16 * 32 * AP);
    const unsigned char* usrc = g_U + (size_t)nh * (16 * 128 * AP);

    if (tid == 0) {
        while (ld_acq(&g_wcnt[nh]) < 128) __nanosleep(64);
        while (ld_acq(&g_vflag[mb]) == 0) __nanosleep(64);
        asm volatile("fence.proxy.async;" ::: "memory");
        mbar_expect(FULL0, CHK);
        bulkcp(sbase, vsrc, V_CHK, FULL0);
        bulkcp(sbase + V_CHK, usrc, U_CHK, FULL0);
        mbar_expect(FULL1, CHK);
        bulkcp(sbase + CHK, vsrc + V_CHK, V_CHK, FULL1);
        bulkcp(sbase + CHK + V_CHK, usrc + U_CHK, U_CHK, FULL1);
    }

    float y[2][4][4];
#pragma unroll
    for (int nt = 0; nt < 2; ++nt)
#pragma unroll
        for (int j = 0; j < 4; ++j)
#pragma unroll
            for (int o = 0; o < 4; ++o) y[nt][j][o] = 0.f;

    const int lrow = lane & 7, grp = lane >> 3;
    const uint32_t laneA = (uint32_t)((wm * 16 + (grp & 1) * 8 + lrow) * AP + (grp >> 1) * 16);
    const uint32_t laneB = (uint32_t)((wn * 16 + (grp >> 1) * 8 + lrow) * AP + (grp & 1) * 16);

#pragma unroll
    for (int g = 0; g < 8; ++g) {
        mbar_wait((g & 1) ? FULL1 : FULL0, (g >> 1) & 1);
        const uint32_t vb = sbase + (g & 1) * CHK;
        const uint32_t ub = vb + V_CHK;

#pragma unroll
        for (int pp = 0; pp < 2; ++pp) {
            const int p = 2 * g + pp;
            float acc[2][4];
#pragma unroll
            for (int nt = 0; nt < 2; ++nt)
#pragma unroll
                for (int j = 0; j < 4; ++j) acc[nt][j] = 0.f;

#pragma unroll
            for (int k0 = 0; k0 < 4; ++k0) {
                uint32_t a[4], r0, r1, r2, r3;
                ldsm4(a[0], a[1], a[2], a[3], vb + pp * (32 * AP) + laneA + k0 * 32);
                ldsm4(r0, r1, r2, r3, ub + pp * (128 * AP) + laneB + k0 * 32);
                uint32_t b01[2] = {r0, r1}, b23[2] = {r2, r3};
                mma16832f8(acc[0], a, b01);
                mma16832f8(acc[1], a, b23);
            }

            const int pr = p >> 2, pc = p & 3;
            const int s0r = c_S0[pr], s1r = c_S1[pr];
            const int s0c = c_S0[pc], s1c = c_S1[pc];
#pragma unroll
            for (int nt = 0; nt < 2; ++nt)
#pragma unroll
                for (int j = 0; j < 4; ++j) {
                    const float m = acc[nt][j];
                    if (s0r * s0c) y[nt][j][0] += (s0r * s0c > 0) ? m : -m;
                    if (s0r * s1c) y[nt][j][1] += (s0r * s1c > 0) ? m : -m;
                    if (s1r * s0c) y[nt][j][2] += (s1r * s0c > 0) ? m : -m;
                    if (s1r * s1c) y[nt][j][3] += (s1r * s1c > 0) ? m : -m;
                }
        }

        if (g < 6) {
            mbar_arrive((g & 1) ? EMPT1 : EMPT0);
            if (tid == 0) {
                mbar_wait((g & 1) ? EMPT1 : EMPT0, (g >> 1) & 1);
                mbar_expect((g & 1) ? FULL1 : FULL0, CHK);
                const uint32_t db = sbase + (g & 1) * CHK;
                bulkcp(db, vsrc + (size_t)(g + 2) * V_CHK, V_CHK,
                       (g & 1) ? FULL1 : FULL0);
                bulkcp(db + V_CHK, usrc + (size_t)(g + 2) * U_CHK, U_CHK,
                       (g & 1) ? FULL1 : FULL0);
            }
        }
    }

    // --- epilogue ---
    const int rr = mb & 127;
    const int trow = rr >> 1, chf = rr & 1;

#pragma unroll
    for (int nt = 0; nt < 2; ++nt)
#pragma unroll
    for (int j = 0; j < 4; ++j) {
        const int tloc = wm * 16 + (lane >> 2) + (j >> 1) * 8;
        const int oc = nh * 128 + wn * 16 + nt * 8 + (lane & 3) * 2 + (j & 1);
        const float sc = g_wscale[oc];
        const float c0 = __ldg(pb0 + oc);
        const float al = __ldg(alpha + oc);
        const float d1 = __ldg(pb1 + oc);

        const int tcol = chf * 32 + tloc;
        float* op = out + (((size_t)(b * COC + oc) * 128 + 2 * trow) * 128 + 2 * tcol);
        float v;
        float2 o0, o1;
        v = y[nt][j][0] * sc + c0; v = v >= 0.f ? v : v * al; o0.x = v + d1;
        v = y[nt][j][1] * sc + c0; v = v >= 0.f ? v : v * al; o0.y = v + d1;
        v = y[nt][j][2] * sc + c0; v = v >= 0.f ? v : v * al; o1.x = v + d1;
        v = y[nt][j][3] * sc + c0; v = v >= 0.f ? v : v * al; o1.y = v + d1;
        *reinterpret_cast<float2*>(op) = o0;
        *reinterpret_cast<float2*>(op + 128) = o1;
    }
}

// ---------------------------------------------------------------- launcher
extern "C" void kernel_launch(void* const* d_in, const int* in_sizes, int n_in,
                              void* d_out, int out_size) {
    const float* x   = (const float*)d_in[0];
    const float* wt  = (const float*)d_in[1];
    const float* mb  = (const float*)d_in[2];
    const float* pb0 = (const float*)d_in[3];
    const float* al  = (const float*)d_in[4];
    const float* pb1 = (const float*)d_in[5];
    float* out = (float*)d_out;

    cudaFuncSetAttribute(fused_kernel, cudaFuncAttributeMaxDynamicSharedMemorySize, SMEM_TOT);

    // 64 wprep + 8 * (128 prep + 128 vtrans + 256 gemm) = 4160 blocks
    fused_kernel<<<4160, 512, SMEM_TOT>>>(x, wt, mb, out, pb0, al, pb1);
}

// round 17
// speedup vs baseline: 1.3673x; 1.0764x over previous
#include <cuda_runtime.h>
#include <cuda_fp8.h>
#include <cstdint>
#include <cmath>

// ---------------------------------------------------------------------------
// BinaryConv2dBBCU_Down via Winograd F(2x2,3x3), all-exact arithmetic, as a
// SINGLE fused pipeline kernel: wprep + per-image [prep -> vtrans -> gemm]
// with monotone flag dependencies. vtrans is SIMD-within-register. The
// At m A fold now uses compile-time coefficient functions (constexpr), so
// it compiles to bare FADDs instead of constant-memory loads + predication.
// ---------------------------------------------------------------------------

#define NB   8
#define CINC 128
#define COC  256
#define HPAD 130
#define AP   144
#define NMB  1024                    // 32-tile M-blocks (32768 tiles total)

// device scratch
__device__ __align__(256) signed char   g_act[(size_t)NB * HPAD * HPAD * CINC];
__device__ __align__(256) unsigned char g_V[(size_t)NMB * 16 * 32 * AP];   // [mb][pos][tile32][144]
__device__ __align__(256) unsigned char g_U[(size_t)2 * 16 * 128 * AP];    // [nh][pos][oc128][144]
__device__ float g_wscale[COC];
__device__ int   g_rowflag[NB][128];   // zero-init, monotone
__device__ int   g_vflag[NMB];         // zero-init, monotone
__device__ int   g_wcnt[2];            // monotone; ==128 => U half ready

// ------------------------------------------------------------- PTX helpers
__device__ __forceinline__ void bulkcp(uint32_t dst, const void* src, uint32_t bytes,
                                       uint32_t mbar) {
    asm volatile("cp.async.bulk.shared::cta.global.mbarrier::complete_tx::bytes "
                 "[%0], [%1], %2, [%3];"
                 :: "r"(dst), "l"(src), "r"(bytes), "r"(mbar) : "memory");
}
__device__ __forceinline__ void mbar_init(uint32_t a, uint32_t cnt) {
    asm volatile("mbarrier.init.shared.b64 [%0], %1;" :: "r"(a), "r"(cnt) : "memory");
}
__device__ __forceinline__ void mbar_expect(uint32_t a, uint32_t bytes) {
    asm volatile("mbarrier.arrive.expect_tx.shared.b64 _, [%0], %1;"
                 :: "r"(a), "r"(bytes) : "memory");
}
__device__ __forceinline__ void mbar_arrive(uint32_t a) {
    asm volatile("mbarrier.arrive.shared.b64 _, [%0];" :: "r"(a) : "memory");
}
__device__ __forceinline__ void mbar_wait(uint32_t a, uint32_t parity) {
    asm volatile(
        "{\n\t.reg .pred P1;\n\t"
        "WAIT_%=:\n\t"
        "mbarrier.try_wait.parity.acquire.cta.shared::cta.b64 P1, [%0], %1, 0x989680;\n\t"
        "@P1 bra.uni DONE_%=;\n\t"
        "bra.uni WAIT_%=;\n\t"
        "DONE_%=:\n\t}"
        :: "r"(a), "r"(parity) : "memory");
}
__device__ __forceinline__ int ld_acq(const int* p) {
    int v;
    asm volatile("ld.global.acquire.gpu.b32 %0, [%1];" : "=r"(v) : "l"(p) : "memory");
    return v;
}
__device__ __forceinline__ void ldsm4(uint32_t& r0, uint32_t& r1, uint32_t& r2, uint32_t& r3,
                                      uint32_t a) {
    asm volatile("ldmatrix.sync.aligned.m8n8.x4.shared.b16 {%0,%1,%2,%3},[%4];\n"
                 : "=r"(r0), "=r"(r1), "=r"(r2), "=r"(r3) : "r"(a));
}
__device__ __forceinline__ void mma16832f8(float* c, const uint32_t* a, const uint32_t* b) {
    asm volatile("mma.sync.aligned.m16n8k32.row.col.f32.e4m3.e4m3.f32 "
                 "{%0,%1,%2,%3},{%4,%5,%6,%7},{%8,%9},{%0,%1,%2,%3};\n"
                 : "+f"(c[0]), "+f"(c[1]), "+f"(c[2]), "+f"(c[3])
                 : "r"(a[0]), "r"(a[1]), "r"(a[2]), "r"(a[3]), "r"(b[0]), "r"(b[1]));
}
// packed e4m3 encode: 4 int8 values in [-4,4] -> 4 e4m3 bytes (exact)
__device__ __forceinline__ uint32_t e4m3_pack4(uint32_t v) {
    const uint32_t sgn = v & 0x80808080u;
    const uint32_t mag = __vabsss4(v);                 // bytes in 0..4
    const uint32_t sel = (mag & 0xFu) | ((mag >> 4) & 0xF0u) |
                         ((mag >> 8) & 0xF00u) | ((mag >> 12) & 0xF000u);
    return __byte_perm(0x44403800u, 0x48u, sel) | sgn; // {0,1,2,3,4}->{0,38,40,44,48}
}
// compile-time At fold coefficients (fully folded in unrolled loops)
__device__ __forceinline__ constexpr int S0f(int i) { return (i == 3) ? 0 : 1; }
__device__ __forceinline__ constexpr int S1f(int i) {
    return (i == 0) ? 0 : ((i == 1) ? 1 : -1);
}

// GEMM smem layout
#define V_CHK  9216                          // 2 pos x 32 tiles x 144
#define U_CHK  36864                         // 2 pos x 128 oc x 144
#define CHK    (V_CHK + U_CHK)               // 46080
#define BAR_OFF (2 * CHK)                    // 92160
#define SMEM_TOT (BAR_OFF + 64)              // 92224 -> 2 CTAs/SM

// ---------------------------------------------------------------- pipeline
// grid: [0,64)                          wprep (4 oc per block)
//       64 + b*512 + [0,128)            prep   image b, pooled row y
//       64 + b*512 + 128 + [0,128)      vtrans image b, rr (trow,chf)
//       64 + b*512 + 256 + [0,256)      gemm   image b, nh*128 + rr
__global__ void __launch_bounds__(512, 2) fused_kernel(
    const float* __restrict__ x, const float* __restrict__ wt,
    const float* __restrict__ mbias,
    float* __restrict__ out,
    const float* __restrict__ pb0, const float* __restrict__ alpha,
    const float* __restrict__ pb1)
{
    extern __shared__ char smem[];
    const int bid = blockIdx.x;
    const int tid = threadIdx.x, lane = tid & 31;

    // ================================================================ wprep
    if (bid < 64) {
        const int oc = bid * 4 + (tid >> 7);
        const int c = tid & 127;
        const float* wp = wt + ((size_t)oc * CINC + c) * 9;
        float v[9]; float s = 0.f;
#pragma unroll
        for (int i = 0; i < 9; ++i) { v[i] = wp[i]; s += fabsf(v[i]); }

        float* red = reinterpret_cast<float*>(smem);
        red[tid] = s;
        __syncthreads();
        for (int o = 64; o > 0; o >>= 1) {
            if (c < o) red[tid] += red[tid + o];
            __syncthreads();
        }
        if (c == 0) g_wscale[oc] = red[tid] * (1.f / 1152.f);

        float sg[9];
#pragma unroll
        for (int i = 0; i < 9; ++i) sg[i] = v[i] > 0.f ? 1.f : (v[i] < 0.f ? -1.f : 0.f);
        float h[4][3];
#pragma unroll
        for (int j = 0; j < 3; ++j) {
            h[0][j] = sg[j];
            h[1][j] = 0.5f * (sg[j] + sg[3 + j] + sg[6 + j]);
            h[2][j] = 0.5f * (sg[j] - sg[3 + j] + sg[6 + j]);
            h[3][j] = sg[6 + j];
        }
        const int nh = oc >> 7, ocl = oc & 127;
#pragma unroll
        for (int r = 0; r < 4; ++r) {
            float a = h[r][0], bb = h[r][1], cc = h[r][2];
            float uu[4] = {a, 0.5f * (a + bb + cc), 0.5f * (a - bb + cc), cc};
#pragma unroll
            for (int q = 0; q < 4; ++q) {
                const int p = r * 4 + q;
                g_U[((size_t)(nh * 16 + p) * 128 + ocl) * AP + c] =
                    (unsigned char)__nv_cvt_float_to_fp8(uu[q], __NV_SATFINITE, __NV_E4M3);
            }
        }
        __threadfence();
        if (c == 0) atomicAdd(&g_wcnt[nh], 1);
        return;
    }

    const int seg = bid - 64;
    const int b = seg >> 9;
    const int off = seg & 511;

    // ================================================================= prep
    if (off < 128) {
        const int y = off;
        const int wrp = tid >> 5;
        signed char* st = reinterpret_cast<signed char*>(smem);   // [x][c] pitch 136

        for (int k = 0; k < 8; ++k) {
            const int c = wrp + 16 * k;
            const float* r0 = x + ((size_t)(b * CINC + c) * 256 + 2 * y) * 256;
            const float* r1 = r0 + 256;
            const float bias = __ldg(mbias + c);
#pragma unroll
            for (int xb = 0; xb < 2; ++xb) {
                const int xo = xb * 64 + lane * 2;
                float4 u = *reinterpret_cast<const float4*>(r0 + 2 * xo);
                float4 v = *reinterpret_cast<const float4*>(r1 + 2 * xo);
                float p0 = (u.x + u.y + v.x + v.y) * 0.25f + bias;
                float p1 = (u.z + u.w + v.z + v.w) * 0.25f + bias;
                st[xo * 136 + c]       = p0 > 0.f ? 1 : (p0 < 0.f ? -1 : 0);
                st[(xo + 1) * 136 + c] = p1 > 0.f ? 1 : (p1 < 0.f ? -1 : 0);
            }
        }
        __syncthreads();

        uint32_t* dst = reinterpret_cast<uint32_t*>(
            g_act + ((size_t)(b * HPAD + (y + 1)) * HPAD) * CINC);
        const char* sp = reinterpret_cast<const char*>(st);
        for (int i = tid; i < 128 * 32; i += 512) {
            const int xr = i >> 5, wd = i & 31;
            dst[(xr + 1) * 32 + wd] = *reinterpret_cast<const uint32_t*>(sp + xr * 136 + wd * 4);
        }

        uint32_t* base = reinterpret_cast<uint32_t*>(g_act + ((size_t)b * HPAD * HPAD) * CINC);
        if (y == 0) {
            for (int i = tid; i < HPAD * 32; i += 512) base[i] = 0u;
        } else if (y == 127) {
            uint32_t* r129 = base + (size_t)129 * HPAD * 32;
            for (int i = tid; i < HPAD * 32; i += 512) r129[i] = 0u;
        }
        uint32_t* rowp = base + (size_t)(y + 1) * HPAD * 32;
        if (tid < 32) rowp[tid] = 0u;
        else if (tid < 64) rowp[129 * 32 + (tid - 32)] = 0u;

        __threadfence();
        __syncthreads();
        if (tid == 0) atomicExch(&g_rowflag[b][y], 1);
        return;
    }

    // ================================================================ vtrans
    if (off < 256) {
        const int rr = off - 128;
        const int mb = b * 128 + rr;
        const int trow = rr >> 1, chf = rr & 1;
        const int c4 = (tid & 31) * 4;
        const int w = tid >> 5;

        if (tid == 0) {
            const int ylo = trow > 0 ? 2 * trow - 1 : 0;
            while (ld_acq(&g_rowflag[b][ylo]) == 0) __nanosleep(64);
            while (ld_acq(&g_rowflag[b][2 * trow]) == 0) __nanosleep(64);
            while (ld_acq(&g_rowflag[b][2 * trow + 1]) == 0) __nanosleep(64);
            if (trow < 63)
                while (ld_acq(&g_rowflag[b][2 * trow + 2]) == 0) __nanosleep(64);
        }
        __syncthreads();

        for (int tt = 0; tt < 2; ++tt) {
            const int tloc = w * 2 + tt;
            const int tx = chf * 32 + tloc;
            uint32_t dw[16];
#pragma unroll
            for (int r = 0; r < 4; ++r)
#pragma unroll
                for (int cx = 0; cx < 4; ++cx)
                    dw[r * 4 + cx] = __ldg(reinterpret_cast<const uint32_t*>(
                        g_act + ((size_t)((b * HPAD + 2 * trow + r) * HPAD) + 2 * tx + cx) * CINC + c4));

            // packed Bt d B across 4 channels at once (values |<=4|, exact)
            uint32_t e[16];
#pragma unroll
            for (int cx = 0; cx < 4; ++cx) {
                e[cx]      = __vsub4(dw[cx],     dw[8 + cx]);
                e[4 + cx]  = __vadd4(dw[4 + cx], dw[8 + cx]);
                e[8 + cx]  = __vsub4(dw[8 + cx], dw[4 + cx]);
                e[12 + cx] = __vsub4(dw[4 + cx], dw[12 + cx]);
            }
            uint32_t outp[16];
#pragma unroll
            for (int r = 0; r < 4; ++r) {
                const int bs = r * 4;
                outp[bs]     = e4m3_pack4(__vsub4(e[bs],     e[bs + 2]));
                outp[bs + 1] = e4m3_pack4(__vadd4(e[bs + 1], e[bs + 2]));
                outp[bs + 2] = e4m3_pack4(__vsub4(e[bs + 2], e[bs + 1]));
                outp[bs + 3] = e4m3_pack4(__vsub4(e[bs + 1], e[bs + 3]));
            }
#pragma unroll
            for (int p = 0; p < 16; ++p)
                *reinterpret_cast<uint32_t*>(
                    g_V + ((size_t)(mb * 16 + p) * 32 + tloc) * AP + c4) = outp[p];
        }

        __threadfence();
        __syncthreads();
        if (tid == 0) atomicExch(&g_vflag[mb], 1);
        return;
    }

    // ================================================================== gemm
    const int cid = off - 256;
    const int nh = cid >> 7;
    const int mb = b * 128 + (cid & 127);
    const int w = tid >> 5;
    const int wm = w >> 3, wn = w & 7;

    const uint32_t sbase = (uint32_t)__cvta_generic_to_shared(smem);
    const uint32_t FULL0 = sbase + BAR_OFF, FULL1 = sbase + BAR_OFF + 8;
    const uint32_t EMPT0 = sbase + BAR_OFF + 16, EMPT1 = sbase + BAR_OFF + 24;

    if (tid == 0) {
        mbar_init(FULL0, 1); mbar_init(FULL1, 1);
        mbar_init(EMPT0, 512); mbar_init(EMPT1, 512);
    }
    __syncthreads();

    const unsigned char* vsrc = g_V + (size_t)mb * (16 * 32 * AP);
    const unsigned char* usrc = g_U + (size_t)nh * (16 * 128 * AP);

    if (tid == 0) {
        while (ld_acq(&g_wcnt[nh]) < 128) __nanosleep(64);
        while (ld_acq(&g_vflag[mb]) == 0) __nanosleep(64);
        asm volatile("fence.proxy.async;" ::: "memory");
        mbar_expect(FULL0, CHK);
        bulkcp(sbase, vsrc, V_CHK, FULL0);
        bulkcp(sbase + V_CHK, usrc, U_CHK, FULL0);
        mbar_expect(FULL1, CHK);
        bulkcp(sbase + CHK, vsrc + V_CHK, V_CHK, FULL1);
        bulkcp(sbase + CHK + V_CHK, usrc + U_CHK, U_CHK, FULL1);
    }

    float y[2][4][4];
#pragma unroll
    for (int nt = 0; nt < 2; ++nt)
#pragma unroll
        for (int j = 0; j < 4; ++j)
#pragma unroll
            for (int o = 0; o < 4; ++o) y[nt][j][o] = 0.f;

    const int lrow = lane & 7, grp = lane >> 3;
    const uint32_t laneA = (uint32_t)((wm * 16 + (grp & 1) * 8 + lrow) * AP + (grp >> 1) * 16);
    const uint32_t laneB = (uint32_t)((wn * 16 + (grp >> 1) * 8 + lrow) * AP + (grp & 1) * 16);

#pragma unroll
    for (int g = 0; g < 8; ++g) {
        mbar_wait((g & 1) ? FULL1 : FULL0, (g >> 1) & 1);
        const uint32_t vb = sbase + (g & 1) * CHK;
        const uint32_t ub = vb + V_CHK;

#pragma unroll
        for (int pp = 0; pp < 2; ++pp) {
            constexpr int dummy = 0; (void)dummy;
            const int p = 2 * g + pp;          // compile-time (g, pp unrolled)
            float acc[2][4];
#pragma unroll
            for (int nt = 0; nt < 2; ++nt)
#pragma unroll
                for (int j = 0; j < 4; ++j) acc[nt][j] = 0.f;

#pragma unroll
            for (int k0 = 0; k0 < 4; ++k0) {
                uint32_t a[4], r0, r1, r2, r3;
                ldsm4(a[0], a[1], a[2], a[3], vb + pp * (32 * AP) + laneA + k0 * 32);
                ldsm4(r0, r1, r2, r3, ub + pp * (128 * AP) + laneB + k0 * 32);
                uint32_t b01[2] = {r0, r1}, b23[2] = {r2, r3};
                mma16832f8(acc[0], a, b01);
                mma16832f8(acc[1], a, b23);
            }

            // compile-time fold coefficients -> bare FADDs
            const int pr = p >> 2, pc = p & 3;
            const int s0r = S0f(pr), s1r = S1f(pr);
            const int s0c = S0f(pc), s1c = S1f(pc);
#pragma unroll
            for (int nt = 0; nt < 2; ++nt)
#pragma unroll
                for (int j = 0; j < 4; ++j) {
                    const float m = acc[nt][j];
                    if (s0r * s0c != 0) y[nt][j][0] += (s0r * s0c > 0) ? m : -m;
                    if (s0r * s1c != 0) y[nt][j][1] += (s0r * s1c > 0) ? m : -m;
                    if (s1r * s0c != 0) y[nt][j][2] += (s1r * s0c > 0) ? m : -m;
                    if (s1r * s1c != 0) y[nt][j][3] += (s1r * s1c > 0) ? m : -m;
                }
        }

        if (g < 6) {
            mbar_arrive((g & 1) ? EMPT1 : EMPT0);
            if (tid == 0) {
                mbar_wait((g & 1) ? EMPT1 : EMPT0, (g >> 1) & 1);
                mbar_expect((g & 1) ? FULL1 : FULL0, CHK);
                const uint32_t db = sbase + (g & 1) * CHK;
                bulkcp(db, vsrc + (size_t)(g + 2) * V_CHK, V_CHK,
                       (g & 1) ? FULL1 : FULL0);
                bulkcp(db + V_CHK, usrc + (size_t)(g + 2) * U_CHK, U_CHK,
                       (g & 1) ? FULL1 : FULL0);
            }
        }
    }

    // --- epilogue ---
    const int rr = mb & 127;
    const int trow = rr >> 1, chf = rr & 1;

#pragma unroll
    for (int nt = 0; nt < 2; ++nt)
#pragma unroll
    for (int j = 0; j < 4; ++j) {
        const int tloc = wm * 16 + (lane >> 2) + (j >> 1) * 8;
        const int oc = nh * 128 + wn * 16 + nt * 8 + (lane & 3) * 2 + (j & 1);
        const float sc = g_wscale[oc];
        const float c0 = __ldg(pb0 + oc);
        const float al = __ldg(alpha + oc);
        const float d1 = __ldg(pb1 + oc);

        const int tcol = chf * 32 + tloc;
        float* op = out + (((size_t)(b * COC + oc) * 128 + 2 * trow) * 128 + 2 * tcol);
        float v;
        float2 o0, o1;
        v = y[nt][j][0] * sc + c0; v = v >= 0.f ? v : v * al; o0.x = v + d1;
        v = y[nt][j][1] * sc + c0; v = v >= 0.f ? v : v * al; o0.y = v + d1;
        v = y[nt][j][2] * sc + c0; v = v >= 0.f ? v : v * al; o1.x = v + d1;
        v = y[nt][j][3] * sc + c0; v = v >= 0.f ? v : v * al; o1.y = v + d1;
        *reinterpret_cast<float2*>(op) = o0;
        *reinterpret_cast<float2*>(op + 128) = o1;
    }
}

// ---------------------------------------------------------------- launcher
extern "C" void kernel_launch(void* const* d_in, const int* in_sizes, int n_in,
                              void* d_out, int out_size) {
    const float* x   = (const float*)d_in[0];
    const float* wt  = (const float*)d_in[1];
    const float* mb  = (const float*)d_in[2];
    const float* pb0 = (const float*)d_in[3];
    const float* al  = (const float*)d_in[4];
    const float* pb1 = (const float*)d_in[5];
    float* out = (float*)d_out;

    cudaFuncSetAttribute(fused_kernel, cudaFuncAttributeMaxDynamicSharedMemorySize, SMEM_TOT);

    // 64 wprep + 8 * (128 prep + 128 vtrans + 256 gemm) = 4160 blocks
    fused_kernel<<<4160, 512, SMEM_TOT>>>(x, wt, mb, out, pb0, al, pb1);
}